// round 11
// baseline (speedup 1.0000x reference)
#include <cuda_runtime.h>
#include <cuda_bf16.h>
#include <cstdint>

// RBF: out[i][j] = exp(-||x_i - y_j||^2), N=M=8192, D=64, fp32.
// dist2 = xn + yn - 2*dot; dot via bf16 hi/lo split on mma.sync (HMMA).
// Round 10 (resubmit): warp-group PING-PONG. 512-thr CTA = two independent
// 8-warp groups, each an R7-style 128x128 pipeline on its own smem (A copy +
// B double buffer). Token mbarriers serialize the MMA mainloops across the
// groups so one group's epilogue (MUFU+STG) always overlaps the other
// group's mainloop (tensor+ldsm). Lockstep phase-bursts eliminated.

#define NN 8192
#define DD 64
#define TILE 128
#define NSM 148
#define NCTA NSM                  // 148, 1 CTA/SM
#define NTHREADS 512
#define TOTTILES (64 * 64)        // 4096 tiles of 128x128

// per-group smem block: A resident (32KB) + B double buffer (64KB)
#define GSMEM 98304
#define AH_OFF 0
#define AL_OFF 16384
#define BH_OFF(buf) (32768 + (buf) * 32768)
#define BL_OFF(buf) (32768 + (buf) * 32768 + 16384)
#define SMEM_DYN_BYTES (2 * GSMEM)   // 192 KB

#define LOG2E      1.4426950408889634f
#define TWO_LOG2E  2.8853900817779268f

__device__ float g_xn[NN];   // ||x_i||^2 * log2(e)
__device__ float g_yn[NN];   // ||y_j||^2 * log2(e)
__device__ __nv_bfloat16 g_xh[NN * DD];
__device__ __nv_bfloat16 g_xl[NN * DD];
__device__ __nv_bfloat16 g_yh[NN * DD];
__device__ __nv_bfloat16 g_yl[NN * DD];

// ------------------------- helpers -----------------------------------------
__device__ __forceinline__ uint32_t smem_u32(const void* p) {
    uint32_t a;
    asm("{ .reg .u64 t; cvta.to.shared.u64 t, %1; cvt.u32.u64 %0, t; }"
        : "=r"(a) : "l"(p));
    return a;
}

__device__ __forceinline__ void cp_async16(uint32_t saddr, const void* gaddr) {
    asm volatile("cp.async.cg.shared.global [%0], [%1], 16;"
                 :: "r"(saddr), "l"(gaddr) : "memory");
}

__device__ __forceinline__ void mbar_init(uint32_t addr, uint32_t cnt) {
    asm volatile("mbarrier.init.shared.b64 [%0], %1;"
                 :: "r"(addr), "r"(cnt) : "memory");
}

__device__ __forceinline__ void cp_arrive_noinc(uint32_t addr) {
    asm volatile("cp.async.mbarrier.arrive.noinc.shared.b64 [%0];"
                 :: "r"(addr) : "memory");
}

__device__ __forceinline__ void mbar_arrive(uint32_t addr) {
    asm volatile("{ .reg .b64 tk; mbarrier.arrive.shared.b64 tk, [%0]; }"
                 :: "r"(addr) : "memory");
}

__device__ __forceinline__ void mbar_wait(uint32_t addr, uint32_t parity) {
    asm volatile(
        "{\n\t.reg .pred P1;\n\t"
        "WL_%=:\n\t"
        "mbarrier.try_wait.parity.acquire.cta.shared::cta.b64 P1, [%0], %1, 0x989680;\n\t"
        "@P1 bra.uni WD_%=;\n\t"
        "bra.uni WL_%=;\n\t"
        "WD_%=:\n\t}"
        :: "r"(addr), "r"(parity) : "memory");
}

__device__ __forceinline__ void ldsm4(uint32_t addr, uint32_t& r0, uint32_t& r1,
                                      uint32_t& r2, uint32_t& r3) {
    asm volatile("ldmatrix.sync.aligned.m8n8.x4.shared.b16 {%0,%1,%2,%3}, [%4];"
                 : "=r"(r0), "=r"(r1), "=r"(r2), "=r"(r3) : "r"(addr));
}

__device__ __forceinline__ void mma16816(float& c0, float& c1, float& c2, float& c3,
                                         uint32_t a0, uint32_t a1, uint32_t a2,
                                         uint32_t a3, uint32_t b0, uint32_t b1) {
    asm volatile(
        "mma.sync.aligned.m16n8k16.row.col.f32.bf16.bf16.f32 "
        "{%0,%1,%2,%3}, {%4,%5,%6,%7}, {%8,%9}, {%0,%1,%2,%3};"
        : "+f"(c0), "+f"(c1), "+f"(c2), "+f"(c3)
        : "r"(a0), "r"(a1), "r"(a2), "r"(a3), "r"(b0), "r"(b1));
}

__device__ __forceinline__ float ex2f(float v) {
    float r;
    asm("ex2.approx.ftz.f32 %0, %1;" : "=f"(r) : "f"(v));
    return r;
}

__device__ __forceinline__ uint32_t swz(uint32_t base, int row, int chunk) {
    return base + row * 128 + (((unsigned)chunk ^ ((unsigned)row & 7u)) << 4);
}

__device__ __forceinline__ void split2(float v0, float v1,
                                       uint32_t& hp, uint32_t& lp) {
    __nv_bfloat16 h0 = __float2bfloat16(v0);
    __nv_bfloat16 h1 = __float2bfloat16(v1);
    __nv_bfloat16 l0 = __float2bfloat16(v0 - __bfloat162float(h0));
    __nv_bfloat16 l1 = __float2bfloat16(v1 - __bfloat162float(h1));
    __nv_bfloat162 hh(h0, h1), ll(l0, l1);
    hp = *reinterpret_cast<uint32_t*>(&hh);
    lp = *reinterpret_cast<uint32_t*>(&ll);
}

// ---------------------------------------------------------------------------
__global__ void presplit_kernel(const float* __restrict__ x,
                                const float* __restrict__ y) {
    int tid = blockIdx.x * blockDim.x + threadIdx.x;
    int row = tid >> 4;
    int q = tid & 15;

    float4 vx = __ldg(reinterpret_cast<const float4*>(x + (size_t)row * DD) + q);
    float4 vy = __ldg(reinterpret_cast<const float4*>(y + (size_t)row * DD) + q);

    uint32_t h0, l0, h1, l1;
    split2(vx.x, vx.y, h0, l0);
    split2(vx.z, vx.w, h1, l1);
    *reinterpret_cast<uint2*>(&g_xh[(size_t)row * DD + q * 4]) = make_uint2(h0, h1);
    *reinterpret_cast<uint2*>(&g_xl[(size_t)row * DD + q * 4]) = make_uint2(l0, l1);
    split2(vy.x, vy.y, h0, l0);
    split2(vy.z, vy.w, h1, l1);
    *reinterpret_cast<uint2*>(&g_yh[(size_t)row * DD + q * 4]) = make_uint2(h0, h1);
    *reinterpret_cast<uint2*>(&g_yl[(size_t)row * DD + q * 4]) = make_uint2(l0, l1);

    float sx = vx.x * vx.x + vx.y * vx.y + vx.z * vx.z + vx.w * vx.w;
    float sy = vy.x * vy.x + vy.y * vy.y + vy.z * vy.z + vy.w * vy.w;
#pragma unroll
    for (int o = 8; o >= 1; o >>= 1) {
        sx += __shfl_xor_sync(0xffffffffu, sx, o, 16);
        sy += __shfl_xor_sync(0xffffffffu, sy, o, 16);
    }
    if (q == 0) {
        g_xn[row] = sx * LOG2E;
        g_yn[row] = sy * LOG2E;
    }
}

// ---------------------------------------------------------------------------
// group tile fills: 256 threads of the group, 16B cp.async into swizzled smem
__device__ __forceinline__ void load_A(uint32_t gbase, int tl, int row0) {
    const __nv_bfloat16* sh = g_xh + (size_t)row0 * DD;
    const __nv_bfloat16* sl = g_xl + (size_t)row0 * DD;
#pragma unroll
    for (int it = 0; it < 4; it++) {
        int idx = tl + 256 * it;   // 0..1023
        int r = idx >> 3;          // row 0..127
        int q = idx & 7;
        cp_async16(swz(gbase + AH_OFF, r, q), sh + (size_t)r * DD + q * 8);
        cp_async16(swz(gbase + AL_OFF, r, q), sl + (size_t)r * DD + q * 8);
    }
}

__device__ __forceinline__ void load_B(uint32_t gbase, int buf, int tl, int col0) {
    const __nv_bfloat16* sh = g_yh + (size_t)col0 * DD;
    const __nv_bfloat16* sl = g_yl + (size_t)col0 * DD;
    const uint32_t bh = gbase + BH_OFF(buf);
    const uint32_t bl = gbase + BL_OFF(buf);
#pragma unroll
    for (int it = 0; it < 4; it++) {
        int idx = tl + 256 * it;
        int r = idx >> 3;
        int q = idx & 7;
        cp_async16(swz(bh, r, q), sh + (size_t)r * DD + q * 8);
        cp_async16(swz(bl, r, q), sl + (size_t)r * DD + q * 8);
    }
}

// ---------------------------------------------------------------------------
// Persistent kernel: 512 threads = 2 groups x 8 warps (2x4 grid each).
// ---------------------------------------------------------------------------
__global__ __launch_bounds__(NTHREADS, 1)
void rbf_mma_kernel(float* __restrict__ out) {
    extern __shared__ __align__(128) char smem_raw[];
    const uint32_t sbase = smem_u32(smem_raw);

    // [0..3]=group0 fill0,fill1,read0,read1; [4..7]=group1; [8,9]=tok0,tok1
    __shared__ __align__(8) uint64_t s_mbar[10];

    const int t    = threadIdx.x;
    const int g    = t >> 8;           // group 0/1
    const int tl   = t & 255;          // thread in group
    const int widg = (t >> 5) & 7;     // warp in group
    const int lane = t & 31;
    const int b    = blockIdx.x;

    const uint32_t gbase  = sbase + g * GSMEM;
    const uint32_t fill_a0 = smem_u32(&s_mbar[g * 4 + 0]);
    const uint32_t fill_a1 = smem_u32(&s_mbar[g * 4 + 1]);
    const uint32_t read_a0 = smem_u32(&s_mbar[g * 4 + 2]);
    const uint32_t read_a1 = smem_u32(&s_mbar[g * 4 + 3]);
    const uint32_t tok_own = smem_u32(&s_mbar[8 + g]);
    const uint32_t tok_oth = smem_u32(&s_mbar[8 + (1 - g)]);

    if (t == 0) {
#pragma unroll
        for (int i = 0; i < 10; i++) mbar_init(smem_u32(&s_mbar[i]), 256);
    }
    __syncthreads();

    // CTA tile run (contiguous, row-major over 64x64 tiles of 128x128)
    const int base  = TOTTILES / NCTA;
    const int rem   = TOTTILES % NCTA;
    const int cnt   = base + (b < rem);
    const int start = (b < rem) ? (base + 1) * b : rem * (base + 1) + base * (b - rem);
    const int cnt_g = (cnt - g + 1) >> 1;   // tiles for this group

    // warp tiling within group: 2x4 warps, warp tile 64x32
    const int m_base = (widg >> 2) * 64;
    const int n_base = (widg & 3) * 32;
    const int a_row = m_base + (lane & 15);
    const int a_half = lane >> 4;
    const int b_row = n_base + ((lane >> 4) & 1) * 8 + (lane & 7);
    const int b_half = (lane >> 3) & 1;
    const int group = lane >> 2;
    const int tig   = lane & 3;

    // prologue for this group
    if (cnt_g > 0) {
        const int id0 = start + g;
        load_A(gbase, tl, (id0 >> 6) * TILE);
        load_B(gbase, 0, tl, (id0 & 63) * TILE);
        cp_arrive_noinc(fill_a0);
    }

    float xnv[4][2];   // persistent per row strip

    for (int u = 0; u < cnt_g; u++) {
        const int id   = start + g + 2 * u;
        const int ti   = id >> 6;
        const int row0 = ti * TILE;
        const int col0 = (id & 63) * TILE;
        const int buf  = u & 1;
        const uint32_t fill_cur = buf ? fill_a1 : fill_a0;
        const uint32_t fill_nxt = buf ? fill_a0 : fill_a1;
        const uint32_t read_cur = buf ? read_a1 : read_a0;
        const uint32_t read_oth = buf ? read_a0 : read_a1;

        // 1. group done reading buf^1 (its mainloop u-1)
        if (u > 0) mbar_wait(read_oth, ((u - 1) >> 1) & 1);

        const bool strip_entry = (u == 0) || (((id - 2) >> 6) != ti);

        // 2. deferred A+B load at row-strip change
        if (u > 0 && strip_entry) {
            load_A(gbase, tl, row0);
            load_B(gbase, buf, tl, col0);
            cp_arrive_noinc(fill_cur);
        }
        // 3. prefetch this group's next B if same row strip
        if (u + 1 < cnt_g && (((id + 2) >> 6) == ti)) {
            load_B(gbase, buf ^ 1, tl, ((id + 2) & 63) * TILE);
            cp_arrive_noinc(fill_nxt);
        }

        // norms
        if (strip_entry) {
#pragma unroll
            for (int m = 0; m < 4; m++) {
                xnv[m][0] = __ldg(&g_xn[row0 + m_base + 16 * m + group]);
                xnv[m][1] = __ldg(&g_xn[row0 + m_base + 16 * m + group + 8]);
            }
        }
        float ynv[4][2];
#pragma unroll
        for (int n = 0; n < 4; n++) {
            ynv[n][0] = __ldg(&g_yn[col0 + n_base + 8 * n + 2 * tig]);
            ynv[n][1] = __ldg(&g_yn[col0 + n_base + 8 * n + 2 * tig + 1]);
        }

        // 4. wait B(u) data ready
        mbar_wait(fill_cur, (u >> 1) & 1);

        // 5. PING-PONG token: serialize mainloops across the two groups.
        //    Order: ML_g0(0), ML_g1(0), ML_g0(1), ML_g1(1), ...
        if (g == 0) {
            if (u > 0) mbar_wait(tok_own, (u - 1) & 1);
        } else {
            mbar_wait(tok_own, u & 1);
        }

        // ---- mainloop (R7 per-warp structure) ----
        const uint32_t bhb = gbase + BH_OFF(buf);
        const uint32_t blb = gbase + BL_OFF(buf);

        float acc[4][4][4];
#pragma unroll
        for (int m = 0; m < 4; m++)
#pragma unroll
            for (int n = 0; n < 4; n++)
#pragma unroll
                for (int e = 0; e < 4; e++) acc[m][n][e] = 0.f;

#pragma unroll
        for (int kc = 0; kc < 4; kc++) {
            const int a_chunk = kc * 2 + a_half;
            const int b_chunk = kc * 2 + b_half;

            uint32_t ah[4][4];
#pragma unroll
            for (int m = 0; m < 4; m++)
                ldsm4(swz(gbase + AH_OFF, a_row + 16 * m, a_chunk),
                      ah[m][0], ah[m][1], ah[m][2], ah[m][3]);
            uint32_t bh[4][2];
#pragma unroll
            for (int p = 0; p < 2; p++)
                ldsm4(swz(bhb, b_row + 16 * p, b_chunk),
                      bh[2 * p][0], bh[2 * p][1], bh[2 * p + 1][0], bh[2 * p + 1][1]);
#pragma unroll
            for (int m = 0; m < 4; m++)
#pragma unroll
                for (int n = 0; n < 4; n++)
                    mma16816(acc[m][n][0], acc[m][n][1], acc[m][n][2], acc[m][n][3],
                             ah[m][0], ah[m][1], ah[m][2], ah[m][3],
                             bh[n][0], bh[n][1]);

            uint32_t bl[4][2];
#pragma unroll
            for (int p = 0; p < 2; p++)
                ldsm4(swz(blb, b_row + 16 * p, b_chunk),
                      bl[2 * p][0], bl[2 * p][1], bl[2 * p + 1][0], bl[2 * p + 1][1]);
#pragma unroll
            for (int m = 0; m < 4; m++)
#pragma unroll
                for (int n = 0; n < 4; n++)
                    mma16816(acc[m][n][0], acc[m][n][1], acc[m][n][2], acc[m][n][3],
                             ah[m][0], ah[m][1], ah[m][2], ah[m][3],
                             bl[n][0], bl[n][1]);

            uint32_t al[4][4];
#pragma unroll
            for (int m = 0; m < 4; m++)
                ldsm4(swz(gbase + AL_OFF, a_row + 16 * m, a_chunk),
                      al[m][0], al[m][1], al[m][2], al[m][3]);
#pragma unroll
            for (int m = 0; m < 4; m++)
#pragma unroll
                for (int n = 0; n < 4; n++)
                    mma16816(acc[m][n][0], acc[m][n][1], acc[m][n][2], acc[m][n][3],
                             al[m][0], al[m][1], al[m][2], al[m][3],
                             bh[n][0], bh[n][1]);
        }

        // 6. done reading smem; hand tensor pipe to the other group
        mbar_arrive(read_cur);
        mbar_arrive(tok_oth);

        // ---- epilogue (regs + global; overlaps other group's mainloop) ----
#pragma unroll
        for (int m = 0; m < 4; m++) {
            const size_t grow0 = (size_t)(row0 + m_base + 16 * m + group) * NN;
            const size_t grow1 = grow0 + (size_t)8 * NN;
#pragma unroll
            for (int n = 0; n < 4; n++) {
                const int gcol = col0 + n_base + 8 * n + 2 * tig;
                float e0 = ex2f(fmaf(TWO_LOG2E, acc[m][n][0], -(xnv[m][0] + ynv[n][0])));
                float e1 = ex2f(fmaf(TWO_LOG2E, acc[m][n][1], -(xnv[m][0] + ynv[n][1])));
                float e2 = ex2f(fmaf(TWO_LOG2E, acc[m][n][2], -(xnv[m][1] + ynv[n][0])));
                float e3 = ex2f(fmaf(TWO_LOG2E, acc[m][n][3], -(xnv[m][1] + ynv[n][1])));
                __stcs(reinterpret_cast<float2*>(out + grow0 + gcol), make_float2(e0, e1));
                __stcs(reinterpret_cast<float2*>(out + grow1 + gcol), make_float2(e2, e3));
            }
        }
    }
}

// ---------------------------------------------------------------------------
extern "C" void kernel_launch(void* const* d_in, const int* in_sizes, int n_in,
                              void* d_out, int out_size) {
    const float* x = (const float*)d_in[0];
    const float* y = (const float*)d_in[1];
    float* out = (float*)d_out;
    (void)in_sizes; (void)n_in; (void)out_size;

    cudaFuncSetAttribute(rbf_mma_kernel,
                         cudaFuncAttributeMaxDynamicSharedMemorySize,
                         SMEM_DYN_BYTES);

    presplit_kernel<<<(NN * DD / 4) / 256, 256>>>(x, y);
    rbf_mma_kernel<<<NCTA, NTHREADS, SMEM_DYN_BYTES>>>(out);
}

// round 13
// speedup vs baseline: 1.1991x; 1.1991x over previous
#include <cuda_runtime.h>
#include <cuda_bf16.h>
#include <cstdint>

// RBF: out[i][j] = exp(-||x_i - y_j||^2), N=M=8192, D=64, fp32.
// dist2 = xn + yn - 2*dot; dot via bf16 hi/lo split on mma.sync (HMMA).
// Round 12 (resubmit; prior attempt died to infra): WARP SPECIALIZATION.
// 512-thr CTA = 8 ML warps (ldsm+mma+STS only; 2/SMSP keeps tensor pipe fed)
// + 8 EPI warps (cp.async fills, exp, STG only). Accumulators handed ML->EPI
// through a swizzled 64KB smem stage, so MUFU/STG/fills overlap the next
// tile's MMAs by construction.

#define NN 8192
#define DD 64
#define TILE 128
#define NSM 148
#define NCTA NSM                  // 148, 1 CTA/SM
#define NTHREADS 512
#define TOTTILES (64 * 64)        // 4096 tiles of 128x128

// smem: A 32K | B buf0 32K | B buf1 32K | acc stage 64K
#define AH_OFF 0
#define AL_OFF 16384
#define BH_OFF(buf) (32768 + (buf) * 32768)
#define BL_OFF(buf) (32768 + (buf) * 32768 + 16384)
#define STAGE_OFF 98304
#define SMEM_DYN_BYTES 163840     // 160 KB

#define LOG2E      1.4426950408889634f
#define TWO_LOG2E  2.8853900817779268f

__device__ float g_xn[NN];   // ||x_i||^2 * log2(e)
__device__ float g_yn[NN];   // ||y_j||^2 * log2(e)
__device__ __nv_bfloat16 g_xh[NN * DD];
__device__ __nv_bfloat16 g_xl[NN * DD];
__device__ __nv_bfloat16 g_yh[NN * DD];
__device__ __nv_bfloat16 g_yl[NN * DD];

// ------------------------- helpers -----------------------------------------
__device__ __forceinline__ uint32_t smem_u32(const void* p) {
    uint32_t a;
    asm("{ .reg .u64 t; cvta.to.shared.u64 t, %1; cvt.u32.u64 %0, t; }"
        : "=r"(a) : "l"(p));
    return a;
}

__device__ __forceinline__ void cp_async16(uint32_t saddr, const void* gaddr) {
    asm volatile("cp.async.cg.shared.global [%0], [%1], 16;"
                 :: "r"(saddr), "l"(gaddr) : "memory");
}

__device__ __forceinline__ void mbar_init(uint32_t addr, uint32_t cnt) {
    asm volatile("mbarrier.init.shared.b64 [%0], %1;"
                 :: "r"(addr), "r"(cnt) : "memory");
}

__device__ __forceinline__ void cp_arrive_noinc(uint32_t addr) {
    asm volatile("cp.async.mbarrier.arrive.noinc.shared.b64 [%0];"
                 :: "r"(addr) : "memory");
}

__device__ __forceinline__ void mbar_arrive(uint32_t addr) {
    asm volatile("{ .reg .b64 tk; mbarrier.arrive.shared.b64 tk, [%0]; }"
                 :: "r"(addr) : "memory");
}

__device__ __forceinline__ void mbar_wait(uint32_t addr, uint32_t parity) {
    asm volatile(
        "{\n\t.reg .pred P1;\n\t"
        "WL_%=:\n\t"
        "mbarrier.try_wait.parity.acquire.cta.shared::cta.b64 P1, [%0], %1, 0x989680;\n\t"
        "@P1 bra.uni WD_%=;\n\t"
        "bra.uni WL_%=;\n\t"
        "WD_%=:\n\t}"
        :: "r"(addr), "r"(parity) : "memory");
}

__device__ __forceinline__ void ldsm4(uint32_t addr, uint32_t& r0, uint32_t& r1,
                                      uint32_t& r2, uint32_t& r3) {
    asm volatile("ldmatrix.sync.aligned.m8n8.x4.shared.b16 {%0,%1,%2,%3}, [%4];"
                 : "=r"(r0), "=r"(r1), "=r"(r2), "=r"(r3) : "r"(addr));
}

__device__ __forceinline__ void mma16816(float& c0, float& c1, float& c2, float& c3,
                                         uint32_t a0, uint32_t a1, uint32_t a2,
                                         uint32_t a3, uint32_t b0, uint32_t b1) {
    asm volatile(
        "mma.sync.aligned.m16n8k16.row.col.f32.bf16.bf16.f32 "
        "{%0,%1,%2,%3}, {%4,%5,%6,%7}, {%8,%9}, {%0,%1,%2,%3};"
        : "+f"(c0), "+f"(c1), "+f"(c2), "+f"(c3)
        : "r"(a0), "r"(a1), "r"(a2), "r"(a3), "r"(b0), "r"(b1));
}

__device__ __forceinline__ float ex2f(float v) {
    float r;
    asm("ex2.approx.ftz.f32 %0, %1;" : "=f"(r) : "f"(v));
    return r;
}

__device__ __forceinline__ uint32_t swz(uint32_t base, int row, int chunk) {
    return base + row * 128 + (((unsigned)chunk ^ ((unsigned)row & 7u)) << 4);
}

// acc stage: float2 units, row-major 128 rows x 64 float2-cols, col XOR
// swizzled with (row&7)<<2 -> >=2-phase (minimum) STS/LDS on both sides.
__device__ __forceinline__ uint32_t stage_addr(uint32_t sbase, int row, int cp) {
    return sbase + STAGE_OFF + row * 512 +
           (((unsigned)cp ^ (((unsigned)row & 7u) << 2)) << 3);
}

__device__ __forceinline__ void sts64(uint32_t addr, float a, float b) {
    asm volatile("st.shared.v2.f32 [%0], {%1, %2};"
                 :: "r"(addr), "f"(a), "f"(b) : "memory");
}

__device__ __forceinline__ void lds64(uint32_t addr, float& a, float& b) {
    asm volatile("ld.shared.v2.f32 {%0, %1}, [%2];"
                 : "=f"(a), "=f"(b) : "r"(addr));
}

__device__ __forceinline__ void split2(float v0, float v1,
                                       uint32_t& hp, uint32_t& lp) {
    __nv_bfloat16 h0 = __float2bfloat16(v0);
    __nv_bfloat16 h1 = __float2bfloat16(v1);
    __nv_bfloat16 l0 = __float2bfloat16(v0 - __bfloat162float(h0));
    __nv_bfloat16 l1 = __float2bfloat16(v1 - __bfloat162float(h1));
    __nv_bfloat162 hh(h0, h1), ll(l0, l1);
    hp = *reinterpret_cast<uint32_t*>(&hh);
    lp = *reinterpret_cast<uint32_t*>(&ll);
}

// ---------------------------------------------------------------------------
__global__ void presplit_kernel(const float* __restrict__ x,
                                const float* __restrict__ y) {
    int tid = blockIdx.x * blockDim.x + threadIdx.x;
    int row = tid >> 4;
    int q = tid & 15;

    float4 vx = __ldg(reinterpret_cast<const float4*>(x + (size_t)row * DD) + q);
    float4 vy = __ldg(reinterpret_cast<const float4*>(y + (size_t)row * DD) + q);

    uint32_t h0, l0, h1, l1;
    split2(vx.x, vx.y, h0, l0);
    split2(vx.z, vx.w, h1, l1);
    *reinterpret_cast<uint2*>(&g_xh[(size_t)row * DD + q * 4]) = make_uint2(h0, h1);
    *reinterpret_cast<uint2*>(&g_xl[(size_t)row * DD + q * 4]) = make_uint2(l0, l1);
    split2(vy.x, vy.y, h0, l0);
    split2(vy.z, vy.w, h1, l1);
    *reinterpret_cast<uint2*>(&g_yh[(size_t)row * DD + q * 4]) = make_uint2(h0, h1);
    *reinterpret_cast<uint2*>(&g_yl[(size_t)row * DD + q * 4]) = make_uint2(l0, l1);

    float sx = vx.x * vx.x + vx.y * vx.y + vx.z * vx.z + vx.w * vx.w;
    float sy = vy.x * vy.x + vy.y * vy.y + vy.z * vy.z + vy.w * vy.w;
#pragma unroll
    for (int o = 8; o >= 1; o >>= 1) {
        sx += __shfl_xor_sync(0xffffffffu, sx, o, 16);
        sy += __shfl_xor_sync(0xffffffffu, sy, o, 16);
    }
    if (q == 0) {
        g_xn[row] = sx * LOG2E;
        g_yn[row] = sy * LOG2E;
    }
}

// ---------------------------------------------------------------------------
// tile fills: executed by the 256 EPI threads (tl in 0..255)
__device__ __forceinline__ void load_A(uint32_t sbase, int tl, int row0) {
    const __nv_bfloat16* sh = g_xh + (size_t)row0 * DD;
    const __nv_bfloat16* sl = g_xl + (size_t)row0 * DD;
#pragma unroll
    for (int it = 0; it < 4; it++) {
        int idx = tl + 256 * it;   // 0..1023
        int r = idx >> 3;          // row 0..127
        int q = idx & 7;
        cp_async16(swz(sbase + AH_OFF, r, q), sh + (size_t)r * DD + q * 8);
        cp_async16(swz(sbase + AL_OFF, r, q), sl + (size_t)r * DD + q * 8);
    }
}

__device__ __forceinline__ void load_B(uint32_t sbase, int buf, int tl, int col0) {
    const __nv_bfloat16* sh = g_yh + (size_t)col0 * DD;
    const __nv_bfloat16* sl = g_yl + (size_t)col0 * DD;
    const uint32_t bh = sbase + BH_OFF(buf);
    const uint32_t bl = sbase + BL_OFF(buf);
#pragma unroll
    for (int it = 0; it < 4; it++) {
        int idx = tl + 256 * it;
        int r = idx >> 3;
        int q = idx & 7;
        cp_async16(swz(bh, r, q), sh + (size_t)r * DD + q * 8);
        cp_async16(swz(bl, r, q), sl + (size_t)r * DD + q * 8);
    }
}

// ---------------------------------------------------------------------------
// Persistent kernel: 512 threads. Warps 0-7 = ML (mma), warps 8-15 = EPI.
// ---------------------------------------------------------------------------
__global__ __launch_bounds__(NTHREADS, 1)
void rbf_mma_kernel(float* __restrict__ out) {
    extern __shared__ __align__(128) char smem_raw[];
    const uint32_t sbase = smem_u32(smem_raw);

    // 0:fill0 1:fill1 2:read0 3:read1 4:stage_full 5:stage_free
    __shared__ __align__(8) uint64_t s_mbar[6];

    const int t    = threadIdx.x;
    const int wid  = t >> 5;
    const int lane = t & 31;
    const int b    = blockIdx.x;
    const bool is_ml = (t < 256);

    const uint32_t fill_a0    = smem_u32(&s_mbar[0]);
    const uint32_t fill_a1    = smem_u32(&s_mbar[1]);
    const uint32_t read_a0    = smem_u32(&s_mbar[2]);
    const uint32_t read_a1    = smem_u32(&s_mbar[3]);
    const uint32_t stage_full = smem_u32(&s_mbar[4]);
    const uint32_t stage_free = smem_u32(&s_mbar[5]);

    if (t == 0) {
#pragma unroll
        for (int i = 0; i < 6; i++) mbar_init(smem_u32(&s_mbar[i]), 256);
    }
    __syncthreads();

    // CTA tile run (contiguous, row-major over 64x64 tiles of 128x128)
    const int base  = TOTTILES / NCTA;
    const int rem   = TOTTILES % NCTA;
    const int cnt   = base + (b < rem);
    const int start = (b < rem) ? (base + 1) * b : rem * (base + 1) + base * (b - rem);

    if (is_ml) {
        // ================= ML warps: ldsm + mma + STS stage ================
        const int m_base = (wid >> 2) * 64;
        const int n_base = (wid & 3) * 32;
        const int a_row = m_base + (lane & 15);
        const int a_half = lane >> 4;
        const int b_row = n_base + ((lane >> 4) & 1) * 8 + (lane & 7);
        const int b_half = (lane >> 3) & 1;
        const int group = lane >> 2;
        const int tig   = lane & 3;

        for (int u = 0; u < cnt; u++) {
            const int buf = u & 1;
            const uint32_t fill_cur = buf ? fill_a1 : fill_a0;
            const uint32_t read_cur = buf ? read_a1 : read_a0;

            mbar_wait(fill_cur, (u >> 1) & 1);

            const uint32_t bhb = sbase + BH_OFF(buf);
            const uint32_t blb = sbase + BL_OFF(buf);

            float acc[4][4][4];
#pragma unroll
            for (int m = 0; m < 4; m++)
#pragma unroll
                for (int n = 0; n < 4; n++)
#pragma unroll
                    for (int e = 0; e < 4; e++) acc[m][n][e] = 0.f;

#pragma unroll
            for (int kc = 0; kc < 4; kc++) {
                const int a_chunk = kc * 2 + a_half;
                const int b_chunk = kc * 2 + b_half;

                uint32_t ah[4][4];
#pragma unroll
                for (int m = 0; m < 4; m++)
                    ldsm4(swz(sbase + AH_OFF, a_row + 16 * m, a_chunk),
                          ah[m][0], ah[m][1], ah[m][2], ah[m][3]);
                uint32_t bh[4][2];
#pragma unroll
                for (int p = 0; p < 2; p++)
                    ldsm4(swz(bhb, b_row + 16 * p, b_chunk),
                          bh[2 * p][0], bh[2 * p][1], bh[2 * p + 1][0], bh[2 * p + 1][1]);
#pragma unroll
                for (int m = 0; m < 4; m++)
#pragma unroll
                    for (int n = 0; n < 4; n++)
                        mma16816(acc[m][n][0], acc[m][n][1], acc[m][n][2], acc[m][n][3],
                                 ah[m][0], ah[m][1], ah[m][2], ah[m][3],
                                 bh[n][0], bh[n][1]);

                uint32_t bl[4][2];
#pragma unroll
                for (int p = 0; p < 2; p++)
                    ldsm4(swz(blb, b_row + 16 * p, b_chunk),
                          bl[2 * p][0], bl[2 * p][1], bl[2 * p + 1][0], bl[2 * p + 1][1]);
#pragma unroll
                for (int m = 0; m < 4; m++)
#pragma unroll
                    for (int n = 0; n < 4; n++)
                        mma16816(acc[m][n][0], acc[m][n][1], acc[m][n][2], acc[m][n][3],
                                 ah[m][0], ah[m][1], ah[m][2], ah[m][3],
                                 bl[n][0], bl[n][1]);

                uint32_t al[4][4];
#pragma unroll
                for (int m = 0; m < 4; m++)
                    ldsm4(swz(sbase + AL_OFF, a_row + 16 * m, a_chunk),
                          al[m][0], al[m][1], al[m][2], al[m][3]);
#pragma unroll
                for (int m = 0; m < 4; m++)
#pragma unroll
                    for (int n = 0; n < 4; n++)
                        mma16816(acc[m][n][0], acc[m][n][1], acc[m][n][2], acc[m][n][3],
                                 al[m][0], al[m][1], al[m][2], al[m][3],
                                 bh[n][0], bh[n][1]);
            }

            // done reading A/B smem for this tile
            mbar_arrive(read_cur);

            // stage must be drained of tile u-1 before overwrite
            if (u > 0) mbar_wait(stage_free, (u - 1) & 1);

#pragma unroll
            for (int m = 0; m < 4; m++) {
                const int r0w = m_base + 16 * m + group;
#pragma unroll
                for (int n = 0; n < 4; n++) {
                    const int cp = (n_base >> 1) + 4 * n + tig;
                    sts64(stage_addr(sbase, r0w, cp), acc[m][n][0], acc[m][n][1]);
                    sts64(stage_addr(sbase, r0w + 8, cp), acc[m][n][2], acc[m][n][3]);
                }
            }
            mbar_arrive(stage_full);
        }
    } else {
        // ============ EPI warps: fills + exp + store (no mma) ==============
        const int tl = t - 256;            // 0..255
        const int we = wid - 8;            // 0..7
        const int row_base = we * 16;      // 16 rows per EPI warp

        // prologue fill
        load_A(sbase, tl, (start >> 6) * TILE);
        load_B(sbase, 0, tl, (start & 63) * TILE);
        cp_arrive_noinc(fill_a0);

        for (int u = 0; u < cnt; u++) {
            const int id   = start + u;
            const int ti   = id >> 6;
            const int row0 = ti * TILE;
            const int col0 = (id & 63) * TILE;
            const int buf  = u & 1;
            const uint32_t fill_cur = buf ? fill_a1 : fill_a0;
            const uint32_t fill_nxt = buf ? fill_a0 : fill_a1;
            const uint32_t read_oth = buf ? read_a0 : read_a1;

            // ML done reading previous tile's buffer (and its A strip)
            if (u > 0) mbar_wait(read_oth, ((u - 1) >> 1) & 1);

            const bool strip_entry = (u == 0) || (((id - 1) >> 6) != ti);
            if (u > 0 && strip_entry) {
                load_A(sbase, tl, row0);
                load_B(sbase, buf, tl, col0);
                cp_arrive_noinc(fill_cur);
            }
            if (u + 1 < cnt && (((id + 1) >> 6) == ti)) {
                load_B(sbase, buf ^ 1, tl, ((id + 1) & 63) * TILE);
                cp_arrive_noinc(fill_nxt);
            }

            // y-norms for this thread's 4 output columns
            const float yn0 = __ldg(&g_yn[col0 + 2 * lane]);
            const float yn1 = __ldg(&g_yn[col0 + 2 * lane + 1]);
            const float yn2 = __ldg(&g_yn[col0 + 64 + 2 * lane]);
            const float yn3 = __ldg(&g_yn[col0 + 64 + 2 * lane + 1]);

            // wait for ML to publish accumulators
            mbar_wait(stage_full, u & 1);

#pragma unroll 4
            for (int i = 0; i < 16; i++) {
                const int r = row_base + i;
                const float xn = __ldg(&g_xn[row0 + r]);
                float d0, d1, d2, d3;
                lds64(stage_addr(sbase, r, lane), d0, d1);
                lds64(stage_addr(sbase, r, lane + 32), d2, d3);
                float e0 = ex2f(fmaf(TWO_LOG2E, d0, -(xn + yn0)));
                float e1 = ex2f(fmaf(TWO_LOG2E, d1, -(xn + yn1)));
                float e2 = ex2f(fmaf(TWO_LOG2E, d2, -(xn + yn2)));
                float e3 = ex2f(fmaf(TWO_LOG2E, d3, -(xn + yn3)));
                const size_t grow = (size_t)(row0 + r) * NN + col0;
                __stcs(reinterpret_cast<float2*>(out + grow + 2 * lane),
                       make_float2(e0, e1));
                __stcs(reinterpret_cast<float2*>(out + grow + 64 + 2 * lane),
                       make_float2(e2, e3));
            }
            mbar_arrive(stage_free);
        }
    }
}

// ---------------------------------------------------------------------------
extern "C" void kernel_launch(void* const* d_in, const int* in_sizes, int n_in,
                              void* d_out, int out_size) {
    const float* x = (const float*)d_in[0];
    const float* y = (const float*)d_in[1];
    float* out = (float*)d_out;
    (void)in_sizes; (void)n_in; (void)out_size;

    cudaFuncSetAttribute(rbf_mma_kernel,
                         cudaFuncAttributeMaxDynamicSharedMemorySize,
                         SMEM_DYN_BYTES);

    presplit_kernel<<<(NN * DD / 4) / 256, 256>>>(x, y);
    rbf_mma_kernel<<<NCTA, NTHREADS, SMEM_DYN_BYTES>>>(out);
}

// round 14
// speedup vs baseline: 1.2285x; 1.0246x over previous
#include <cuda_runtime.h>
#include <cuda_bf16.h>
#include <cstdint>

// RBF: out[i][j] = exp(-||x_i - y_j||^2), N=M=8192, D=64, fp32.
// dist2 = xn + yn - 2*dot; dot via bf16 hi/lo split on mma.sync (HMMA).
// Round 14: warp specialization (8 ML + 8 EPI warps) with DOUBLE-BUFFERED
// accumulator stage (2x64KB) so ML never blocks on EPI's drain, and a
// 128-bit EPI datapath (LDS.128 stage reads, STG.128 stores, float4 norms).

#define NN 8192
#define DD 64
#define TILE 128
#define NSM 148
#define NCTA NSM                  // 148, 1 CTA/SM
#define NTHREADS 512
#define TOTTILES (64 * 64)        // 4096 tiles of 128x128

// smem: A 32K | B buf0 32K | B buf1 32K | stage0 64K | stage1 64K
#define AH_OFF 0
#define AL_OFF 16384
#define BH_OFF(buf) (32768 + (buf) * 32768)
#define BL_OFF(buf) (32768 + (buf) * 32768 + 16384)
#define STAGE_OFF(s) (98304 + (s) * 65536)
#define SMEM_DYN_BYTES 229376     // 224 KB

#define LOG2E      1.4426950408889634f
#define TWO_LOG2E  2.8853900817779268f

__device__ float g_xn[NN];   // ||x_i||^2 * log2(e)
__device__ float g_yn[NN];   // ||y_j||^2 * log2(e)
__device__ __nv_bfloat16 g_xh[NN * DD];
__device__ __nv_bfloat16 g_xl[NN * DD];
__device__ __nv_bfloat16 g_yh[NN * DD];
__device__ __nv_bfloat16 g_yl[NN * DD];

// ------------------------- helpers -----------------------------------------
__device__ __forceinline__ uint32_t smem_u32(const void* p) {
    uint32_t a;
    asm("{ .reg .u64 t; cvta.to.shared.u64 t, %1; cvt.u32.u64 %0, t; }"
        : "=r"(a) : "l"(p));
    return a;
}

__device__ __forceinline__ void cp_async16(uint32_t saddr, const void* gaddr) {
    asm volatile("cp.async.cg.shared.global [%0], [%1], 16;"
                 :: "r"(saddr), "l"(gaddr) : "memory");
}

__device__ __forceinline__ void mbar_init(uint32_t addr, uint32_t cnt) {
    asm volatile("mbarrier.init.shared.b64 [%0], %1;"
                 :: "r"(addr), "r"(cnt) : "memory");
}

__device__ __forceinline__ void cp_arrive_noinc(uint32_t addr) {
    asm volatile("cp.async.mbarrier.arrive.noinc.shared.b64 [%0];"
                 :: "r"(addr) : "memory");
}

__device__ __forceinline__ void mbar_arrive(uint32_t addr) {
    asm volatile("{ .reg .b64 tk; mbarrier.arrive.shared.b64 tk, [%0]; }"
                 :: "r"(addr) : "memory");
}

__device__ __forceinline__ void mbar_wait(uint32_t addr, uint32_t parity) {
    asm volatile(
        "{\n\t.reg .pred P1;\n\t"
        "WL_%=:\n\t"
        "mbarrier.try_wait.parity.acquire.cta.shared::cta.b64 P1, [%0], %1, 0x989680;\n\t"
        "@P1 bra.uni WD_%=;\n\t"
        "bra.uni WL_%=;\n\t"
        "WD_%=:\n\t}"
        :: "r"(addr), "r"(parity) : "memory");
}

__device__ __forceinline__ void ldsm4(uint32_t addr, uint32_t& r0, uint32_t& r1,
                                      uint32_t& r2, uint32_t& r3) {
    asm volatile("ldmatrix.sync.aligned.m8n8.x4.shared.b16 {%0,%1,%2,%3}, [%4];"
                 : "=r"(r0), "=r"(r1), "=r"(r2), "=r"(r3) : "r"(addr));
}

__device__ __forceinline__ void mma16816(float& c0, float& c1, float& c2, float& c3,
                                         uint32_t a0, uint32_t a1, uint32_t a2,
                                         uint32_t a3, uint32_t b0, uint32_t b1) {
    asm volatile(
        "mma.sync.aligned.m16n8k16.row.col.f32.bf16.bf16.f32 "
        "{%0,%1,%2,%3}, {%4,%5,%6,%7}, {%8,%9}, {%0,%1,%2,%3};"
        : "+f"(c0), "+f"(c1), "+f"(c2), "+f"(c3)
        : "r"(a0), "r"(a1), "r"(a2), "r"(a3), "r"(b0), "r"(b1));
}

__device__ __forceinline__ float ex2f(float v) {
    float r;
    asm("ex2.approx.ftz.f32 %0, %1;" : "=f"(r) : "f"(v));
    return r;
}

__device__ __forceinline__ uint32_t swz(uint32_t base, int row, int chunk) {
    return base + row * 128 + (((unsigned)chunk ^ ((unsigned)row & 7u)) << 4);
}

// acc stage: float2 units, 128 rows x 64 float2-cols (512B/row), col index
// XOR-swizzled with (row&7)<<2. XOR touches bits>=2 only, so even/odd cp
// pairs stay 16B-adjacent -> EPI can LDS.128.
__device__ __forceinline__ uint32_t stage_addr(uint32_t stage_base, int row, int cp) {
    return stage_base + row * 512 +
           (((unsigned)cp ^ (((unsigned)row & 7u) << 2)) << 3);
}

__device__ __forceinline__ void sts64(uint32_t addr, float a, float b) {
    asm volatile("st.shared.v2.f32 [%0], {%1, %2};"
                 :: "r"(addr), "f"(a), "f"(b) : "memory");
}

__device__ __forceinline__ void lds128(uint32_t addr, float& a, float& b,
                                       float& c, float& d) {
    asm volatile("ld.shared.v4.f32 {%0, %1, %2, %3}, [%4];"
                 : "=f"(a), "=f"(b), "=f"(c), "=f"(d) : "r"(addr));
}

__device__ __forceinline__ void split2(float v0, float v1,
                                       uint32_t& hp, uint32_t& lp) {
    __nv_bfloat16 h0 = __float2bfloat16(v0);
    __nv_bfloat16 h1 = __float2bfloat16(v1);
    __nv_bfloat16 l0 = __float2bfloat16(v0 - __bfloat162float(h0));
    __nv_bfloat16 l1 = __float2bfloat16(v1 - __bfloat162float(h1));
    __nv_bfloat162 hh(h0, h1), ll(l0, l1);
    hp = *reinterpret_cast<uint32_t*>(&hh);
    lp = *reinterpret_cast<uint32_t*>(&ll);
}

// ---------------------------------------------------------------------------
__global__ void presplit_kernel(const float* __restrict__ x,
                                const float* __restrict__ y) {
    int tid = blockIdx.x * blockDim.x + threadIdx.x;
    int row = tid >> 4;
    int q = tid & 15;

    float4 vx = __ldg(reinterpret_cast<const float4*>(x + (size_t)row * DD) + q);
    float4 vy = __ldg(reinterpret_cast<const float4*>(y + (size_t)row * DD) + q);

    uint32_t h0, l0, h1, l1;
    split2(vx.x, vx.y, h0, l0);
    split2(vx.z, vx.w, h1, l1);
    *reinterpret_cast<uint2*>(&g_xh[(size_t)row * DD + q * 4]) = make_uint2(h0, h1);
    *reinterpret_cast<uint2*>(&g_xl[(size_t)row * DD + q * 4]) = make_uint2(l0, l1);
    split2(vy.x, vy.y, h0, l0);
    split2(vy.z, vy.w, h1, l1);
    *reinterpret_cast<uint2*>(&g_yh[(size_t)row * DD + q * 4]) = make_uint2(h0, h1);
    *reinterpret_cast<uint2*>(&g_yl[(size_t)row * DD + q * 4]) = make_uint2(l0, l1);

    float sx = vx.x * vx.x + vx.y * vx.y + vx.z * vx.z + vx.w * vx.w;
    float sy = vy.x * vy.x + vy.y * vy.y + vy.z * vy.z + vy.w * vy.w;
#pragma unroll
    for (int o = 8; o >= 1; o >>= 1) {
        sx += __shfl_xor_sync(0xffffffffu, sx, o, 16);
        sy += __shfl_xor_sync(0xffffffffu, sy, o, 16);
    }
    if (q == 0) {
        g_xn[row] = sx * LOG2E;
        g_yn[row] = sy * LOG2E;
    }
}

// ---------------------------------------------------------------------------
// tile fills: executed by the 256 EPI threads (tl in 0..255)
__device__ __forceinline__ void load_A(uint32_t sbase, int tl, int row0) {
    const __nv_bfloat16* sh = g_xh + (size_t)row0 * DD;
    const __nv_bfloat16* sl = g_xl + (size_t)row0 * DD;
#pragma unroll
    for (int it = 0; it < 4; it++) {
        int idx = tl + 256 * it;   // 0..1023
        int r = idx >> 3;          // row 0..127
        int q = idx & 7;
        cp_async16(swz(sbase + AH_OFF, r, q), sh + (size_t)r * DD + q * 8);
        cp_async16(swz(sbase + AL_OFF, r, q), sl + (size_t)r * DD + q * 8);
    }
}

__device__ __forceinline__ void load_B(uint32_t sbase, int buf, int tl, int col0) {
    const __nv_bfloat16* sh = g_yh + (size_t)col0 * DD;
    const __nv_bfloat16* sl = g_yl + (size_t)col0 * DD;
    const uint32_t bh = sbase + BH_OFF(buf);
    const uint32_t bl = sbase + BL_OFF(buf);
#pragma unroll
    for (int it = 0; it < 4; it++) {
        int idx = tl + 256 * it;
        int r = idx >> 3;
        int q = idx & 7;
        cp_async16(swz(bh, r, q), sh + (size_t)r * DD + q * 8);
        cp_async16(swz(bl, r, q), sl + (size_t)r * DD + q * 8);
    }
}

// ---------------------------------------------------------------------------
// Persistent kernel: 512 threads. Warps 0-7 = ML (mma), warps 8-15 = EPI.
// ---------------------------------------------------------------------------
__global__ __launch_bounds__(NTHREADS, 1)
void rbf_mma_kernel(float* __restrict__ out) {
    extern __shared__ __align__(128) char smem_raw[];
    const uint32_t sbase = smem_u32(smem_raw);

    // 0:fill0 1:fill1 2:read0 3:read1 4:full0 5:full1 6:free0 7:free1
    __shared__ __align__(8) uint64_t s_mbar[8];

    const int t    = threadIdx.x;
    const int wid  = t >> 5;
    const int lane = t & 31;
    const int b    = blockIdx.x;
    const bool is_ml = (t < 256);

    const uint32_t fill_a0 = smem_u32(&s_mbar[0]);
    const uint32_t fill_a1 = smem_u32(&s_mbar[1]);
    const uint32_t read_a0 = smem_u32(&s_mbar[2]);
    const uint32_t read_a1 = smem_u32(&s_mbar[3]);
    const uint32_t full_a0 = smem_u32(&s_mbar[4]);
    const uint32_t full_a1 = smem_u32(&s_mbar[5]);
    const uint32_t free_a0 = smem_u32(&s_mbar[6]);
    const uint32_t free_a1 = smem_u32(&s_mbar[7]);

    if (t == 0) {
#pragma unroll
        for (int i = 0; i < 8; i++) mbar_init(smem_u32(&s_mbar[i]), 256);
    }
    __syncthreads();

    // CTA tile run (contiguous, row-major over 64x64 tiles of 128x128)
    const int base  = TOTTILES / NCTA;
    const int rem   = TOTTILES % NCTA;
    const int cnt   = base + (b < rem);
    const int start = (b < rem) ? (base + 1) * b : rem * (base + 1) + base * (b - rem);

    if (is_ml) {
        // ================= ML warps: ldsm + mma + STS stage ================
        const int m_base = (wid >> 2) * 64;
        const int n_base = (wid & 3) * 32;
        const int a_row = m_base + (lane & 15);
        const int a_half = lane >> 4;
        const int b_row = n_base + ((lane >> 4) & 1) * 8 + (lane & 7);
        const int b_half = (lane >> 3) & 1;
        const int group = lane >> 2;
        const int tig   = lane & 3;

        for (int u = 0; u < cnt; u++) {
            const int buf = u & 1;
            const uint32_t fill_cur = buf ? fill_a1 : fill_a0;
            const uint32_t read_cur = buf ? read_a1 : read_a0;
            const uint32_t full_cur = buf ? full_a1 : full_a0;
            const uint32_t free_cur = buf ? free_a1 : free_a0;

            mbar_wait(fill_cur, (u >> 1) & 1);

            const uint32_t bhb = sbase + BH_OFF(buf);
            const uint32_t blb = sbase + BL_OFF(buf);

            float acc[4][4][4];
#pragma unroll
            for (int m = 0; m < 4; m++)
#pragma unroll
                for (int n = 0; n < 4; n++)
#pragma unroll
                    for (int e = 0; e < 4; e++) acc[m][n][e] = 0.f;

#pragma unroll
            for (int kc = 0; kc < 4; kc++) {
                const int a_chunk = kc * 2 + a_half;
                const int b_chunk = kc * 2 + b_half;

                uint32_t ah[4][4];
#pragma unroll
                for (int m = 0; m < 4; m++)
                    ldsm4(swz(sbase + AH_OFF, a_row + 16 * m, a_chunk),
                          ah[m][0], ah[m][1], ah[m][2], ah[m][3]);
                uint32_t bh[4][2];
#pragma unroll
                for (int p = 0; p < 2; p++)
                    ldsm4(swz(bhb, b_row + 16 * p, b_chunk),
                          bh[2 * p][0], bh[2 * p][1], bh[2 * p + 1][0], bh[2 * p + 1][1]);
#pragma unroll
                for (int m = 0; m < 4; m++)
#pragma unroll
                    for (int n = 0; n < 4; n++)
                        mma16816(acc[m][n][0], acc[m][n][1], acc[m][n][2], acc[m][n][3],
                                 ah[m][0], ah[m][1], ah[m][2], ah[m][3],
                                 bh[n][0], bh[n][1]);

                uint32_t bl[4][2];
#pragma unroll
                for (int p = 0; p < 2; p++)
                    ldsm4(swz(blb, b_row + 16 * p, b_chunk),
                          bl[2 * p][0], bl[2 * p][1], bl[2 * p + 1][0], bl[2 * p + 1][1]);
#pragma unroll
                for (int m = 0; m < 4; m++)
#pragma unroll
                    for (int n = 0; n < 4; n++)
                        mma16816(acc[m][n][0], acc[m][n][1], acc[m][n][2], acc[m][n][3],
                                 ah[m][0], ah[m][1], ah[m][2], ah[m][3],
                                 bl[n][0], bl[n][1]);

                uint32_t al[4][4];
#pragma unroll
                for (int m = 0; m < 4; m++)
                    ldsm4(swz(sbase + AL_OFF, a_row + 16 * m, a_chunk),
                          al[m][0], al[m][1], al[m][2], al[m][3]);
#pragma unroll
                for (int m = 0; m < 4; m++)
#pragma unroll
                    for (int n = 0; n < 4; n++)
                        mma16816(acc[m][n][0], acc[m][n][1], acc[m][n][2], acc[m][n][3],
                                 al[m][0], al[m][1], al[m][2], al[m][3],
                                 bh[n][0], bh[n][1]);
            }

            // done reading A/B smem for this tile
            mbar_arrive(read_cur);

            // stage buffer (u&1) must be drained of tile u-2
            if (u >= 2) mbar_wait(free_cur, ((u >> 1) - 1) & 1);

            const uint32_t stg = sbase + STAGE_OFF(buf);
#pragma unroll
            for (int m = 0; m < 4; m++) {
                const int r0w = m_base + 16 * m + group;
#pragma unroll
                for (int n = 0; n < 4; n++) {
                    const int cp = (n_base >> 1) + 4 * n + tig;
                    sts64(stage_addr(stg, r0w, cp), acc[m][n][0], acc[m][n][1]);
                    sts64(stage_addr(stg, r0w + 8, cp), acc[m][n][2], acc[m][n][3]);
                }
            }
            mbar_arrive(full_cur);
        }
    } else {
        // ============ EPI warps: fills + exp + store (no mma) ==============
        const int tl = t - 256;            // 0..255
        const int we = wid - 8;            // 0..7
        const int row_base = we * 16;      // 16 rows per EPI warp

        // prologue fill
        load_A(sbase, tl, (start >> 6) * TILE);
        load_B(sbase, 0, tl, (start & 63) * TILE);
        cp_arrive_noinc(fill_a0);

        for (int u = 0; u < cnt; u++) {
            const int id   = start + u;
            const int ti   = id >> 6;
            const int row0 = ti * TILE;
            const int col0 = (id & 63) * TILE;
            const int buf  = u & 1;
            const uint32_t fill_cur = buf ? fill_a1 : fill_a0;
            const uint32_t fill_nxt = buf ? fill_a0 : fill_a1;
            const uint32_t read_oth = buf ? read_a0 : read_a1;
            const uint32_t full_cur = buf ? full_a1 : full_a0;
            const uint32_t free_cur = buf ? free_a1 : free_a0;

            // ML done reading previous tile's buffer (and its A strip)
            if (u > 0) mbar_wait(read_oth, ((u - 1) >> 1) & 1);

            const bool strip_entry = (u == 0) || (((id - 1) >> 6) != ti);
            if (u > 0 && strip_entry) {
                load_A(sbase, tl, row0);
                load_B(sbase, buf, tl, col0);
                cp_arrive_noinc(fill_cur);
            }
            if (u + 1 < cnt && (((id + 1) >> 6) == ti)) {
                load_B(sbase, buf ^ 1, tl, ((id + 1) & 63) * TILE);
                cp_arrive_noinc(fill_nxt);
            }

            // y-norms: 4 consecutive cols per thread
            const float4 yn4 = __ldg(reinterpret_cast<const float4*>(
                                         g_yn + col0 + 4 * lane));

            // wait for ML to publish this tile's accumulators
            mbar_wait(full_cur, (u >> 1) & 1);

            const uint32_t stg = sbase + STAGE_OFF(buf);
#pragma unroll 4
            for (int i = 0; i < 16; i++) {
                const int r = row_base + i;
                const float xn = __ldg(&g_xn[row0 + r]);
                float d0, d1, d2, d3;
                lds128(stage_addr(stg, r, 2 * lane), d0, d1, d2, d3);
                float4 e;
                e.x = ex2f(fmaf(TWO_LOG2E, d0, -(xn + yn4.x)));
                e.y = ex2f(fmaf(TWO_LOG2E, d1, -(xn + yn4.y)));
                e.z = ex2f(fmaf(TWO_LOG2E, d2, -(xn + yn4.z)));
                e.w = ex2f(fmaf(TWO_LOG2E, d3, -(xn + yn4.w)));
                __stcs(reinterpret_cast<float4*>(
                           out + (size_t)(row0 + r) * NN + col0 + 4 * lane), e);
            }
            mbar_arrive(free_cur);
        }
    }
}

// ---------------------------------------------------------------------------
extern "C" void kernel_launch(void* const* d_in, const int* in_sizes, int n_in,
                              void* d_out, int out_size) {
    const float* x = (const float*)d_in[0];
    const float* y = (const float*)d_in[1];
    float* out = (float*)d_out;
    (void)in_sizes; (void)n_in; (void)out_size;

    cudaFuncSetAttribute(rbf_mma_kernel,
                         cudaFuncAttributeMaxDynamicSharedMemorySize,
                         SMEM_DYN_BYTES);

    presplit_kernel<<<(NN * DD / 4) / 256, 256>>>(x, y);
    rbf_mma_kernel<<<NCTA, NTHREADS, SMEM_DYN_BYTES>>>(out);
}